// round 8
// baseline (speedup 1.0000x reference)
#include <cuda_runtime.h>
#include <cuda_bf16.h>
#include <cstdint>

#define HID 128
#define NHEAD 8
#define HD 16
#define MAXN 50000
#define MAXE 500000

typedef unsigned long long ull;

// ---------------- static device scratch ----------------
__device__ float g_q[MAXN * HID];
__device__ float g_k[MAXN * HID];
__device__ float g_v[MAXN * HID];
__device__ float g_xr[MAXN * HID];
__device__ float g_num[MAXN * HID];
__device__ float g_z[MAXN * NHEAD];
__device__ float g_e[(size_t)MAXE * HID];     // e rows, PERMUTED into CSR order
__device__ int   g_is64;
// CSR by destination
__device__ int g_deg[MAXN];
__device__ int g_off[MAXN + 1];
__device__ int g_pos[MAXN];
__device__ int g_srcl[MAXE];                  // src node per CSR slot
__device__ int g_perm[MAXE];                  // edge id -> CSR slot
// 5 weights: 4 chunks each (hi-half0, hi-half1, lo-half0, lo-half1), 64x128 bf16 swizzled
__device__ __nv_bfloat16 g_wt[5][4][64 * 128];

// ---------------- helpers ----------------
__device__ __forceinline__ uint32_t smem_u32(const void* p) {
    uint32_t a;
    asm("{ .reg .u64 t; cvta.to.shared.u64 t, %1; cvt.u32.u64 %0, t; }" : "=r"(a) : "l"(p));
    return a;
}

// A tile [128 rows x 128 k] bf16: two 64-k blocks of 16KB, 128B rows, XOR swizzle
__device__ __forceinline__ uint32_t swzA(int row, int k) {
    uint32_t off = ((uint32_t)(k >> 6) << 14) + ((uint32_t)row << 7) + ((uint32_t)(k & 63) << 1);
    return off ^ ((off >> 3) & 0x70);
}
// B tile [64 rows x 128 k] bf16: two 64-k blocks of 8KB
__device__ __forceinline__ uint32_t swzB(int row, int k) {
    uint32_t off = ((uint32_t)(k >> 6) << 13) + ((uint32_t)row << 7) + ((uint32_t)(k & 63) << 1);
    return off ^ ((off >> 3) & 0x70);
}

__device__ __forceinline__ void ldsm4(uint32_t* r, uint32_t addr) {
    asm volatile("ldmatrix.sync.aligned.m8n8.x4.shared.b16 {%0,%1,%2,%3}, [%4];"
                 : "=r"(r[0]), "=r"(r[1]), "=r"(r[2]), "=r"(r[3]) : "r"(addr));
}

__device__ __forceinline__ void mma_bf16(float* d, const uint32_t* a, uint32_t b0, uint32_t b1) {
    asm("mma.sync.aligned.m16n8k16.row.col.f32.bf16.bf16.f32 "
        "{%0,%1,%2,%3}, {%4,%5,%6,%7}, {%8,%9}, {%0,%1,%2,%3};"
        : "+f"(d[0]), "+f"(d[1]), "+f"(d[2]), "+f"(d[3])
        : "r"(a[0]), "r"(a[1]), "r"(a[2]), "r"(a[3]), "r"(b0), "r"(b1));
}

// smem layout (GEMM kernels)
#define SM_AHI  0
#define SM_ALO  32768
#define SM_BHI  65536
#define SM_BLO  81920
#define SM_TOTAL 98304

// ---------------- small kernels ----------------
__global__ void detect_kernel(const void* idx, long long total_elems) {
    if (threadIdx.x == 0 && blockIdx.x == 0) {
        const long long* p = (const long long*)idx;
        long long n = total_elems / 2;
        if (n > 256) n = 256;
        int is64 = 1;
        for (long long i = 0; i < n; i++) {
            long long v = p[i];
            if (v < 0 || v >= (1LL << 31)) is64 = 0;
        }
        g_is64 = is64;
    }
}

__global__ void zero_deg_kernel(int N) {
    int i = blockIdx.x * blockDim.x + threadIdx.x;
    if (i < N) g_deg[i] = 0;
}

__global__ void count_kernel(const void* __restrict__ idx, int E) {
    int e = blockIdx.x * 256 + threadIdx.x;
    if (e >= E) return;
    int d;
    if (g_is64) d = (int)((const long long*)idx)[e + E];
    else        d = ((const int*)idx)[e + E];
    atomicAdd(&g_deg[d], 1);
}

// single-block exclusive scan over g_deg -> g_off, g_pos
__global__ void scan_kernel(int N, int E) {
    __shared__ int sums[1024];
    int t = threadIdx.x;
    int C = (N + 1023) / 1024;
    int b = t * C;
    int hi = b + C; if (hi > N) hi = N;
    int s = 0;
    for (int i = b; i < hi; i++) s += g_deg[i];
    sums[t] = s;
    __syncthreads();
    for (int ofs = 1; ofs < 1024; ofs <<= 1) {
        int v = (t >= ofs) ? sums[t - ofs] : 0;
        __syncthreads();
        sums[t] += v;
        __syncthreads();
    }
    int run = (t == 0) ? 0 : sums[t - 1];
    for (int i = b; i < hi; i++) {
        g_off[i] = run;
        g_pos[i] = run;
        run += g_deg[i];
    }
    if (t == 1023) g_off[N] = E;
}

__global__ void scatter_kernel(const void* __restrict__ idx, int E) {
    int e = blockIdx.x * 256 + threadIdx.x;
    if (e >= E) return;
    int s, d;
    if (g_is64) {
        const long long* p = (const long long*)idx;
        s = (int)p[e]; d = (int)p[e + E];
    } else {
        const int* p = (const int*)idx;
        s = p[e]; d = p[e + E];
    }
    int p = atomicAdd(&g_pos[d], 1);
    g_srcl[p] = s;
    g_perm[e] = p;
}

// W ([in=128,out=128] row-major) -> B[n][k]=W[k][n]; hi/lo bf16; per-half swizzled chunks
__global__ void prep_w_kernel(const float* W0, const float* W1, const float* W2,
                              const float* W3, const float* W4) {
    const float* W = W0;
    if (blockIdx.x == 1) W = W1;
    else if (blockIdx.x == 2) W = W2;
    else if (blockIdx.x == 3) W = W3;
    else if (blockIdx.x == 4) W = W4;
    for (int i = threadIdx.x; i < 128 * 128; i += blockDim.x) {
        int n = i & 127, k = i >> 7;
        float x = W[k * 128 + n];               // coalesced over n
        __nv_bfloat16 hv = __float2bfloat16(x);
        __nv_bfloat16 lv = __float2bfloat16(x - __bfloat162float(hv));
        int half = n >> 6, n64 = n & 63;
        uint32_t sw = swzB(n64, k);
        *(__nv_bfloat16*)((char*)g_wt[blockIdx.x][half]     + sw) = hv;
        *(__nv_bfloat16*)((char*)g_wt[blockIdx.x][2 + half] + sw) = lv;
    }
}

// ---------------- staging ----------------
__device__ __forceinline__ void stage_A(const float* __restrict__ Asrc, int rows_valid,
                                        char* sm, int tid)
{
    char* Ahi = sm + SM_AHI;
    char* Alo = sm + SM_ALO;
    for (int i = tid; i < 4096; i += 256) {
        int r = i >> 5;
        int c4 = (i & 31) << 2;
        float4 x;
        if (r < rows_valid) x = *(const float4*)(Asrc + (size_t)r * HID + c4);
        else x = make_float4(0.f, 0.f, 0.f, 0.f);
        __nv_bfloat162 h01, h23, l01, l23;
        float hx, hy;
        h01.x = __float2bfloat16(x.x); hx = __bfloat162float(h01.x);
        h01.y = __float2bfloat16(x.y); hy = __bfloat162float(h01.y);
        l01.x = __float2bfloat16(x.x - hx);
        l01.y = __float2bfloat16(x.y - hy);
        h23.x = __float2bfloat16(x.z); hx = __bfloat162float(h23.x);
        h23.y = __float2bfloat16(x.w); hy = __bfloat162float(h23.y);
        l23.x = __float2bfloat16(x.z - hx);
        l23.y = __float2bfloat16(x.w - hy);
        uint32_t sw = swzA(r, c4);
        *(__nv_bfloat162*)(Ahi + sw)     = h01;
        *(__nv_bfloat162*)(Ahi + sw + 4) = h23;
        *(__nv_bfloat162*)(Alo + sw)     = l01;
        *(__nv_bfloat162*)(Alo + sw + 4) = l23;
    }
}

__device__ __forceinline__ void stage_B(int wi, int h, char* sm, int tid)
{
    const float4* sH = (const float4*)g_wt[wi][h];
    const float4* sL = (const float4*)g_wt[wi][2 + h];
    float4* dH = (float4*)(sm + SM_BHI);
    float4* dL = (float4*)(sm + SM_BLO);
    for (int i = tid; i < 1024; i += 256) { dH[i] = sH[i]; dL[i] = sL[i]; }
}

// ---------------- fragment load for one ks step ----------------
__device__ __forceinline__ void load_frags(uint32_t smb, int arow, int acoff,
                                           int brow, int bcoff, int k0,
                                           uint32_t ahi[2][4], uint32_t alo[2][4],
                                           uint32_t bhi[2][4], uint32_t blo[2][4])
{
    uint32_t aoff0 = swzA(arow, k0 + acoff);
    uint32_t aoff1 = swzA(arow + 16, k0 + acoff);
    ldsm4(ahi[0], smb + SM_AHI + aoff0);
    ldsm4(ahi[1], smb + SM_AHI + aoff1);
    ldsm4(alo[0], smb + SM_ALO + aoff0);
    ldsm4(alo[1], smb + SM_ALO + aoff1);
#pragma unroll
    for (int p = 0; p < 2; p++) {
        uint32_t boff = swzB(brow + p * 16, k0 + bcoff);
        ldsm4(bhi[p], smb + SM_BHI + boff);
        ldsm4(blo[p], smb + SM_BLO + boff);
    }
}

// ---------------- HMMA mainloop: warp tile 32x32, 3-pass, double-buffered frags ----------------
__device__ __forceinline__ void hmma_loop(uint32_t smb, int lane, int wm, int wn,
                                          float acc[2][4][4])
{
#pragma unroll
    for (int mi = 0; mi < 2; mi++)
#pragma unroll
        for (int nj = 0; nj < 4; nj++)
#pragma unroll
            for (int t = 0; t < 4; t++) acc[mi][nj][t] = 0.f;

    int arow = wm + (lane & 15);
    int acoff = (lane >> 4) << 3;
    int brow = wn + ((lane >> 4) << 3) + (lane & 7);
    int bcoff = lane & 8;

    uint32_t ahi[2][2][4], alo[2][2][4], bhi[2][2][4], blo[2][2][4];
    load_frags(smb, arow, acoff, brow, bcoff, 0, ahi[0], alo[0], bhi[0], blo[0]);

#pragma unroll
    for (int ks = 0; ks < 8; ks++) {
        int cur = ks & 1;
        if (ks < 7)
            load_frags(smb, arow, acoff, brow, bcoff, (ks + 1) * 16,
                       ahi[cur ^ 1], alo[cur ^ 1], bhi[cur ^ 1], blo[cur ^ 1]);
#pragma unroll
        for (int mi = 0; mi < 2; mi++) {
#pragma unroll
            for (int nj = 0; nj < 4; nj++) {
                int p = nj >> 1, hh = (nj & 1) * 2;
                mma_bf16(acc[mi][nj], ahi[cur][mi], bhi[cur][p][hh], bhi[cur][p][hh + 1]);
                mma_bf16(acc[mi][nj], ahi[cur][mi], blo[cur][p][hh], blo[cur][p][hh + 1]);
                mma_bf16(acc[mi][nj], alo[cur][mi], bhi[cur][p][hh], bhi[cur][p][hh + 1]);
            }
        }
    }
}

// ---------------- node kernel: 4 fused projections, BN=64 halves ----------------
__global__ __launch_bounds__(256, 2) void node_hmma_kernel(
    const float* __restrict__ X,
    const float* __restrict__ bq, const float* __restrict__ bk,
    const float* __restrict__ bv, const float* __restrict__ bs, int M)
{
    extern __shared__ char sm[];
    uint32_t smb = smem_u32(sm);
    int tid = threadIdx.x;
    int lane = tid & 31, w = tid >> 5;
    int wm = (w & 3) * 32, wn = (w >> 2) * 32;
    int mBase = blockIdx.x * 128;
    int rv = M - mBase; if (rv > 128) rv = 128;

    stage_A(X + (size_t)mBase * HID, rv, sm, tid);

    const float* biases[4] = {bq, bk, bv, bs};
    float* outs[4] = {g_q, g_k, g_v, g_xr};

#pragma unroll 1
    for (int wi = 0; wi < 4; wi++) {
#pragma unroll 1
        for (int h = 0; h < 2; h++) {
            __syncthreads();
            stage_B(wi, h, sm, tid);
            __syncthreads();

            float acc[2][4][4];
            hmma_loop(smb, lane, wm, wn, acc);

            const float* bias = biases[wi];
            float* out = outs[wi];
            int r0 = mBase + wm + (lane >> 2);
            int cbase = h * 64 + wn + (lane & 3) * 2;
#pragma unroll
            for (int mi = 0; mi < 2; mi++) {
#pragma unroll
                for (int nj = 0; nj < 4; nj++) {
                    int c = cbase + nj * 8;
                    float b0 = __ldg(bias + c), b1 = __ldg(bias + c + 1);
                    int r = r0 + mi * 16;
                    if (r < M)
                        *(float2*)(out + (size_t)r * HID + c) =
                            make_float2(acc[mi][nj][0] + b0, acc[mi][nj][1] + b1);
                    if (r + 8 < M)
                        *(float2*)(out + (size_t)(r + 8) * HID + c) =
                            make_float2(acc[mi][nj][2] + b0, acc[mi][nj][3] + b1);
                }
            }
        }
    }
}

// ---------------- e-GEMM: e = angle @ We, stored PERMUTED to CSR slots ----------------
__global__ __launch_bounds__(256, 2) void egemm_hmma_kernel(
    const float* __restrict__ angle, int E)
{
    extern __shared__ char sm[];
    uint32_t smb = smem_u32(sm);
    int tid = threadIdx.x;
    int lane = tid & 31, w = tid >> 5;
    int wm = (w & 3) * 32, wn = (w >> 2) * 32;
    int eBase = blockIdx.x * 128;
    int rv = E - eBase; if (rv > 128) rv = 128;

    stage_A(angle + (size_t)eBase * HID, rv, sm, tid);

    // permuted destination rows for this thread's 4 output rows
    int r0 = eBase + wm + (lane >> 2);
    long long prow[4];
#pragma unroll
    for (int t = 0; t < 4; t++) {
        int r = r0 + t * 8;     // rows r0, r0+8, r0+16, r0+24
        prow[t] = (r < E) ? (long long)g_perm[r] : -1;
    }

#pragma unroll 1
    for (int h = 0; h < 2; h++) {
        __syncthreads();
        stage_B(4, h, sm, tid);
        __syncthreads();

        float acc[2][4][4];
        hmma_loop(smb, lane, wm, wn, acc);

        int cbase = h * 64 + wn + (lane & 3) * 2;
#pragma unroll
        for (int mi = 0; mi < 2; mi++) {
#pragma unroll
            for (int nj = 0; nj < 4; nj++) {
                int c = cbase + nj * 8;
                long long p0 = prow[mi * 2];
                long long p1 = prow[mi * 2 + 1];
                if (p0 >= 0)
                    __stcs((float2*)(g_e + (size_t)p0 * HID + c),
                           make_float2(acc[mi][nj][0], acc[mi][nj][1]));
                if (p1 >= 0)
                    __stcs((float2*)(g_e + (size_t)p1 * HID + c),
                           make_float2(acc[mi][nj][2], acc[mi][nj][3]));
            }
        }
    }
}

// ---------------- attention gather: warp per node, sequential e, zero atomics ----------------
__global__ __launch_bounds__(256) void attn_gather_kernel(int N)
{
    int warp = threadIdx.x >> 5;
    int lane = threadIdx.x & 31;
    int n = blockIdx.x * 8 + warp;
    if (n >= N) return;
    int c = lane * 4;

    float4 q4 = *(const float4*)(g_q + (size_t)n * HID + c);
    float4 acc = make_float4(0.f, 0.f, 0.f, 0.f);
    float zacc = 0.f;

    int beg = g_off[n], end = g_off[n + 1];
    int s_next = (beg < end) ? g_srcl[beg] : 0;

#pragma unroll 2
    for (int i = beg; i < end; i++) {
        int s = s_next;
        if (i + 1 < end) s_next = g_srcl[i + 1];
        float4 e4 = __ldcs((const float4*)(g_e + (size_t)i * HID + c));
        float4 k4 = *(const float4*)(g_k + (size_t)s * HID + c);
        float4 v4 = *(const float4*)(g_v + (size_t)s * HID + c);

        float part = q4.x * (k4.x + e4.x) + q4.y * (k4.y + e4.y)
                   + q4.z * (k4.z + e4.z) + q4.w * (k4.w + e4.w);
        part += __shfl_xor_sync(0xffffffffu, part, 1);
        part += __shfl_xor_sync(0xffffffffu, part, 2);
        float a = __expf(part * 0.25f);   // /sqrt(16); alpha bounded, no max-shift needed
        zacc += a;
        acc.x += a * (v4.x + e4.x);
        acc.y += a * (v4.y + e4.y);
        acc.z += a * (v4.z + e4.z);
        acc.w += a * (v4.w + e4.w);
    }

    *(float4*)(g_num + (size_t)n * HID + c) = acc;
    if ((lane & 3) == 0) g_z[(size_t)n * NHEAD + (lane >> 2)] = zacc;
}

// ---------------- finalize ----------------
__global__ __launch_bounds__(256) void finalize_kernel(
    const float* __restrict__ x, const float* __restrict__ Wbeta,
    const float* __restrict__ gamma, const float* __restrict__ lbeta,
    float* __restrict__ out, int N)
{
    int warp = threadIdx.x >> 5;
    int lane = threadIdx.x & 31;
    int n = blockIdx.x * 8 + warp;
    if (n >= N) return;
    int c = lane * 4;

    float4 num = *(const float4*)(g_num + (size_t)n * HID + c);
    float z = g_z[(size_t)n * NHEAD + (lane >> 2)];
    float inv = z > 0.f ? 1.f / z : 0.f;
    float4 o = make_float4(num.x * inv, num.y * inv, num.z * inv, num.w * inv);
    float4 xr = *(const float4*)(g_xr + (size_t)n * HID + c);

    float4 wb0 = *(const float4*)(Wbeta + c);
    float4 wb1 = *(const float4*)(Wbeta + 128 + c);
    float4 wb2 = *(const float4*)(Wbeta + 256 + c);
    float dot = o.x * wb0.x + o.y * wb0.y + o.z * wb0.z + o.w * wb0.w
              + xr.x * wb1.x + xr.y * wb1.y + xr.z * wb1.z + xr.w * wb1.w
              + (o.x - xr.x) * wb2.x + (o.y - xr.y) * wb2.y
              + (o.z - xr.z) * wb2.z + (o.w - xr.w) * wb2.w;
#pragma unroll
    for (int m = 16; m; m >>= 1) dot += __shfl_xor_sync(0xffffffffu, dot, m);
    float beta = 1.f / (1.f + __expf(-dot));

    float4 g;
    g.x = beta * xr.x + (1.f - beta) * o.x;
    g.y = beta * xr.y + (1.f - beta) * o.y;
    g.z = beta * xr.z + (1.f - beta) * o.z;
    g.w = beta * xr.w + (1.f - beta) * o.w;

    float sgm = g.x + g.y + g.z + g.w;
#pragma unroll
    for (int m = 16; m; m >>= 1) sgm += __shfl_xor_sync(0xffffffffu, sgm, m);
    float mu = sgm * (1.f / 128.f);

    float dx = g.x - mu, dy = g.y - mu, dz = g.z - mu, dw = g.w - mu;
    float vs = dx * dx + dy * dy + dz * dz + dw * dw;
#pragma unroll
    for (int m = 16; m; m >>= 1) vs += __shfl_xor_sync(0xffffffffu, vs, m);
    float rstd = rsqrtf(vs * (1.f / 128.f) + 1e-5f);

    float4 gm = *(const float4*)(gamma + c);
    float4 lb = *(const float4*)(lbeta + c);
    float4 xin = *(const float4*)(x + (size_t)n * HID + c);

    float4 res;
    float y;
    y = dx * rstd * gm.x + lb.x; res.x = xin.x + fmaxf(y, 0.f);
    y = dy * rstd * gm.y + lb.y; res.y = xin.y + fmaxf(y, 0.f);
    y = dz * rstd * gm.z + lb.z; res.z = xin.z + fmaxf(y, 0.f);
    y = dw * rstd * gm.w + lb.w; res.w = xin.w + fmaxf(y, 0.f);
    *(float4*)(out + (size_t)n * HID + c) = res;
}

// ---------------- launch ----------------
extern "C" void kernel_launch(void* const* d_in, const int* in_sizes, int n_in,
                              void* d_out, int out_size)
{
    const float* edge_state = (const float*)d_in[0];
    const void*  idx        = d_in[1];
    const float* angle      = (const float*)d_in[2];
    const float* Wq = (const float*)d_in[3];
    const float* bq = (const float*)d_in[4];
    const float* Wk = (const float*)d_in[5];
    const float* bk = (const float*)d_in[6];
    const float* Wv = (const float*)d_in[7];
    const float* bv = (const float*)d_in[8];
    const float* We = (const float*)d_in[9];
    const float* Ws = (const float*)d_in[10];
    const float* bs = (const float*)d_in[11];
    const float* Wbeta = (const float*)d_in[12];
    const float* gamma = (const float*)d_in[13];
    const float* lbeta = (const float*)d_in[14];

    int N = in_sizes[0] / HID;
    int E = in_sizes[2] / HID;

    cudaFuncSetAttribute(node_hmma_kernel, cudaFuncAttributeMaxDynamicSharedMemorySize, SM_TOTAL);
    cudaFuncSetAttribute(egemm_hmma_kernel, cudaFuncAttributeMaxDynamicSharedMemorySize, SM_TOTAL);

    detect_kernel<<<1, 32>>>(idx, (long long)in_sizes[1]);
    prep_w_kernel<<<5, 128>>>(Wq, Wk, Wv, Ws, We);

    // CSR build (by destination), also produces edge->slot permutation
    zero_deg_kernel<<<(N + 255) / 256, 256>>>(N);
    count_kernel<<<(E + 255) / 256, 256>>>(idx, E);
    scan_kernel<<<1, 1024>>>(N, E);
    scatter_kernel<<<(E + 255) / 256, 256>>>(idx, E);

    node_hmma_kernel<<<(N + 127) / 128, 256, SM_TOTAL>>>(edge_state, bq, bk, bv, bs, N);

    egemm_hmma_kernel<<<(E + 127) / 128, 256, SM_TOTAL>>>(angle, E);

    attn_gather_kernel<<<(N + 7) / 8, 256>>>(N);

    finalize_kernel<<<(N + 7) / 8, 256>>>(edge_state, Wbeta, gamma, lbeta,
                                          (float*)d_out, N);
}

// round 9
// speedup vs baseline: 1.0534x; 1.0534x over previous
#include <cuda_runtime.h>
#include <cuda_bf16.h>
#include <cstdint>

#define HID 128
#define NHEAD 8
#define HD 16
#define MAXN 50000
#define MAXE 500000

typedef unsigned long long ull;

// ---------------- static device scratch ----------------
__device__ float g_q[MAXN * HID];
__device__ float g_k[MAXN * HID];
__device__ float g_v[MAXN * HID];
__device__ float g_xr[MAXN * HID];
__device__ float g_num[MAXN * HID];
__device__ float g_z[MAXN * NHEAD];
__device__ float g_e[(size_t)MAXE * HID];     // e rows, PERMUTED into CSR order
__device__ int   g_is64;
// CSR by destination
__device__ int g_deg[MAXN];
__device__ int g_off[MAXN + 1];
__device__ int g_pos[MAXN];
__device__ int g_srcl[MAXE];                  // src node per CSR slot
__device__ int g_perm[MAXE];                  // edge id -> CSR slot
// 5 weights: 4 chunks each (hi-half0, hi-half1, lo-half0, lo-half1), 64x128 bf16 swizzled
__device__ __nv_bfloat16 g_wt[5][4][64 * 128];

// ---------------- helpers ----------------
__device__ __forceinline__ uint32_t smem_u32(const void* p) {
    uint32_t a;
    asm("{ .reg .u64 t; cvta.to.shared.u64 t, %1; cvt.u32.u64 %0, t; }" : "=r"(a) : "l"(p));
    return a;
}

// A tile [128 rows x 128 k] bf16: two 64-k blocks of 16KB, 128B rows, XOR swizzle
__device__ __forceinline__ uint32_t swzA(int row, int k) {
    uint32_t off = ((uint32_t)(k >> 6) << 14) + ((uint32_t)row << 7) + ((uint32_t)(k & 63) << 1);
    return off ^ ((off >> 3) & 0x70);
}
// B tile [64 rows x 128 k] bf16: two 64-k blocks of 8KB
__device__ __forceinline__ uint32_t swzB(int row, int k) {
    uint32_t off = ((uint32_t)(k >> 6) << 13) + ((uint32_t)row << 7) + ((uint32_t)(k & 63) << 1);
    return off ^ ((off >> 3) & 0x70);
}

__device__ __forceinline__ void ldsm4(uint32_t* r, uint32_t addr) {
    asm volatile("ldmatrix.sync.aligned.m8n8.x4.shared.b16 {%0,%1,%2,%3}, [%4];"
                 : "=r"(r[0]), "=r"(r[1]), "=r"(r[2]), "=r"(r[3]) : "r"(addr));
}

__device__ __forceinline__ void mma_bf16(float* d, const uint32_t* a, uint32_t b0, uint32_t b1) {
    asm("mma.sync.aligned.m16n8k16.row.col.f32.bf16.bf16.f32 "
        "{%0,%1,%2,%3}, {%4,%5,%6,%7}, {%8,%9}, {%0,%1,%2,%3};"
        : "+f"(d[0]), "+f"(d[1]), "+f"(d[2]), "+f"(d[3])
        : "r"(a[0]), "r"(a[1]), "r"(a[2]), "r"(a[3]), "r"(b0), "r"(b1));
}

// smem layout (GEMM kernels)
#define SM_AHI  0
#define SM_ALO  32768
#define SM_BHI  65536
#define SM_BLO  81920
#define SM_TOTAL 98304

// ---------------- small kernels ----------------
__global__ void detect_kernel(const void* idx, long long total_elems) {
    if (threadIdx.x == 0 && blockIdx.x == 0) {
        const long long* p = (const long long*)idx;
        long long n = total_elems / 2;
        if (n > 256) n = 256;
        int is64 = 1;
        for (long long i = 0; i < n; i++) {
            long long v = p[i];
            if (v < 0 || v >= (1LL << 31)) is64 = 0;
        }
        g_is64 = is64;
    }
}

__global__ void zero_deg_kernel(int N) {
    int i = blockIdx.x * blockDim.x + threadIdx.x;
    if (i < N) g_deg[i] = 0;
}

__global__ void count_kernel(const void* __restrict__ idx, int E) {
    int e = blockIdx.x * 256 + threadIdx.x;
    if (e >= E) return;
    int d;
    if (g_is64) d = (int)((const long long*)idx)[e + E];
    else        d = ((const int*)idx)[e + E];
    atomicAdd(&g_deg[d], 1);
}

// single-block exclusive scan over g_deg -> g_off, g_pos
__global__ void scan_kernel(int N, int E) {
    __shared__ int sums[1024];
    int t = threadIdx.x;
    int C = (N + 1023) / 1024;
    int b = t * C;
    int hi = b + C; if (hi > N) hi = N;
    int s = 0;
    for (int i = b; i < hi; i++) s += g_deg[i];
    sums[t] = s;
    __syncthreads();
    for (int ofs = 1; ofs < 1024; ofs <<= 1) {
        int v = (t >= ofs) ? sums[t - ofs] : 0;
        __syncthreads();
        sums[t] += v;
        __syncthreads();
    }
    int run = (t == 0) ? 0 : sums[t - 1];
    for (int i = b; i < hi; i++) {
        g_off[i] = run;
        g_pos[i] = run;
        run += g_deg[i];
    }
    if (t == 1023) g_off[N] = E;
}

__global__ void scatter_kernel(const void* __restrict__ idx, int E) {
    int e = blockIdx.x * 256 + threadIdx.x;
    if (e >= E) return;
    int s, d;
    if (g_is64) {
        const long long* p = (const long long*)idx;
        s = (int)p[e]; d = (int)p[e + E];
    } else {
        const int* p = (const int*)idx;
        s = p[e]; d = p[e + E];
    }
    int p = atomicAdd(&g_pos[d], 1);
    g_srcl[p] = s;
    g_perm[e] = p;
}

// W ([in=128,out=128] row-major) -> B[n][k]=W[k][n]; hi/lo bf16; per-half swizzled chunks
__global__ void prep_w_kernel(const float* W0, const float* W1, const float* W2,
                              const float* W3, const float* W4) {
    const float* W = W0;
    if (blockIdx.x == 1) W = W1;
    else if (blockIdx.x == 2) W = W2;
    else if (blockIdx.x == 3) W = W3;
    else if (blockIdx.x == 4) W = W4;
    for (int i = threadIdx.x; i < 128 * 128; i += blockDim.x) {
        int n = i & 127, k = i >> 7;
        float x = W[k * 128 + n];               // coalesced over n
        __nv_bfloat16 hv = __float2bfloat16(x);
        __nv_bfloat16 lv = __float2bfloat16(x - __bfloat162float(hv));
        int half = n >> 6, n64 = n & 63;
        uint32_t sw = swzB(n64, k);
        *(__nv_bfloat16*)((char*)g_wt[blockIdx.x][half]     + sw) = hv;
        *(__nv_bfloat16*)((char*)g_wt[blockIdx.x][2 + half] + sw) = lv;
    }
}

// ---------------- staging ----------------
__device__ __forceinline__ void stage_A(const float* __restrict__ Asrc, int rows_valid,
                                        char* sm, int tid)
{
    char* Ahi = sm + SM_AHI;
    char* Alo = sm + SM_ALO;
    for (int i = tid; i < 4096; i += 256) {
        int r = i >> 5;
        int c4 = (i & 31) << 2;
        float4 x;
        if (r < rows_valid) x = *(const float4*)(Asrc + (size_t)r * HID + c4);
        else x = make_float4(0.f, 0.f, 0.f, 0.f);
        __nv_bfloat162 h01, h23, l01, l23;
        float hx, hy;
        h01.x = __float2bfloat16(x.x); hx = __bfloat162float(h01.x);
        h01.y = __float2bfloat16(x.y); hy = __bfloat162float(h01.y);
        l01.x = __float2bfloat16(x.x - hx);
        l01.y = __float2bfloat16(x.y - hy);
        h23.x = __float2bfloat16(x.z); hx = __bfloat162float(h23.x);
        h23.y = __float2bfloat16(x.w); hy = __bfloat162float(h23.y);
        l23.x = __float2bfloat16(x.z - hx);
        l23.y = __float2bfloat16(x.w - hy);
        uint32_t sw = swzA(r, c4);
        *(__nv_bfloat162*)(Ahi + sw)     = h01;
        *(__nv_bfloat162*)(Ahi + sw + 4) = h23;
        *(__nv_bfloat162*)(Alo + sw)     = l01;
        *(__nv_bfloat162*)(Alo + sw + 4) = l23;
    }
}

__device__ __forceinline__ void stage_B(int wi, int h, char* sm, int tid)
{
    const float4* sH = (const float4*)g_wt[wi][h];
    const float4* sL = (const float4*)g_wt[wi][2 + h];
    float4* dH = (float4*)(sm + SM_BHI);
    float4* dL = (float4*)(sm + SM_BLO);
    for (int i = tid; i < 1024; i += 256) { dH[i] = sH[i]; dL[i] = sL[i]; }
}

// ---------------- HMMA mainloop: warp tile 32x32, 3-pass bf16 hi/lo (single-buffer) ----------------
__device__ __forceinline__ void hmma_loop(uint32_t smb, int lane, int wm, int wn,
                                          float acc[2][4][4])
{
#pragma unroll
    for (int mi = 0; mi < 2; mi++)
#pragma unroll
        for (int nj = 0; nj < 4; nj++)
#pragma unroll
            for (int t = 0; t < 4; t++) acc[mi][nj][t] = 0.f;

    int arow = wm + (lane & 15);
    int acoff = (lane >> 4) << 3;
    int brow = wn + ((lane >> 4) << 3) + (lane & 7);
    int bcoff = lane & 8;

#pragma unroll
    for (int ks = 0; ks < 8; ks++) {
        int k0 = ks * 16;
        uint32_t aoff0 = swzA(arow, k0 + acoff);
        uint32_t aoff1 = swzA(arow + 16, k0 + acoff);
        uint32_t ahi[2][4], alo[2][4];
        ldsm4(ahi[0], smb + SM_AHI + aoff0);
        ldsm4(ahi[1], smb + SM_AHI + aoff1);
        ldsm4(alo[0], smb + SM_ALO + aoff0);
        ldsm4(alo[1], smb + SM_ALO + aoff1);

        uint32_t bhi[2][4], blo[2][4];
#pragma unroll
        for (int p = 0; p < 2; p++) {
            uint32_t boff = swzB(brow + p * 16, k0 + bcoff);
            ldsm4(bhi[p], smb + SM_BHI + boff);
            ldsm4(blo[p], smb + SM_BLO + boff);
        }

#pragma unroll
        for (int mi = 0; mi < 2; mi++) {
#pragma unroll
            for (int nj = 0; nj < 4; nj++) {
                int p = nj >> 1, hh = (nj & 1) * 2;
                mma_bf16(acc[mi][nj], ahi[mi], bhi[p][hh], bhi[p][hh + 1]);
                mma_bf16(acc[mi][nj], ahi[mi], blo[p][hh], blo[p][hh + 1]);
                mma_bf16(acc[mi][nj], alo[mi], bhi[p][hh], bhi[p][hh + 1]);
            }
        }
    }
}

// ---------------- node kernel: 4 fused projections, BN=64 halves ----------------
__global__ __launch_bounds__(256, 2) void node_hmma_kernel(
    const float* __restrict__ X,
    const float* __restrict__ bq, const float* __restrict__ bk,
    const float* __restrict__ bv, const float* __restrict__ bs, int M)
{
    extern __shared__ char sm[];
    uint32_t smb = smem_u32(sm);
    int tid = threadIdx.x;
    int lane = tid & 31, w = tid >> 5;
    int wm = (w & 3) * 32, wn = (w >> 2) * 32;
    int mBase = blockIdx.x * 128;
    int rv = M - mBase; if (rv > 128) rv = 128;

    stage_A(X + (size_t)mBase * HID, rv, sm, tid);

    const float* biases[4] = {bq, bk, bv, bs};
    float* outs[4] = {g_q, g_k, g_v, g_xr};

#pragma unroll 1
    for (int wi = 0; wi < 4; wi++) {
#pragma unroll 1
        for (int h = 0; h < 2; h++) {
            __syncthreads();
            stage_B(wi, h, sm, tid);
            __syncthreads();

            float acc[2][4][4];
            hmma_loop(smb, lane, wm, wn, acc);

            const float* bias = biases[wi];
            float* out = outs[wi];
            int r0 = mBase + wm + (lane >> 2);
            int cbase = h * 64 + wn + (lane & 3) * 2;
#pragma unroll
            for (int mi = 0; mi < 2; mi++) {
#pragma unroll
                for (int nj = 0; nj < 4; nj++) {
                    int c = cbase + nj * 8;
                    float b0 = __ldg(bias + c), b1 = __ldg(bias + c + 1);
                    int r = r0 + mi * 16;
                    if (r < M)
                        *(float2*)(out + (size_t)r * HID + c) =
                            make_float2(acc[mi][nj][0] + b0, acc[mi][nj][1] + b1);
                    if (r + 8 < M)
                        *(float2*)(out + (size_t)(r + 8) * HID + c) =
                            make_float2(acc[mi][nj][2] + b0, acc[mi][nj][3] + b1);
                }
            }
        }
    }
}

// ---------------- e-GEMM: e = angle @ We, stored PERMUTED to CSR slots ----------------
__global__ __launch_bounds__(256, 2) void egemm_hmma_kernel(
    const float* __restrict__ angle, int E)
{
    extern __shared__ char sm[];
    uint32_t smb = smem_u32(sm);
    int tid = threadIdx.x;
    int lane = tid & 31, w = tid >> 5;
    int wm = (w & 3) * 32, wn = (w >> 2) * 32;
    int eBase = blockIdx.x * 128;
    int rv = E - eBase; if (rv > 128) rv = 128;

    stage_A(angle + (size_t)eBase * HID, rv, sm, tid);

    // permuted destination rows for this thread's 4 output rows
    int r0 = eBase + wm + (lane >> 2);
    long long prow[4];
#pragma unroll
    for (int t = 0; t < 4; t++) {
        int r = r0 + t * 8;     // rows r0, r0+8, r0+16, r0+24
        prow[t] = (r < E) ? (long long)g_perm[r] : -1;
    }

#pragma unroll 1
    for (int h = 0; h < 2; h++) {
        __syncthreads();
        stage_B(4, h, sm, tid);
        __syncthreads();

        float acc[2][4][4];
        hmma_loop(smb, lane, wm, wn, acc);

        int cbase = h * 64 + wn + (lane & 3) * 2;
#pragma unroll
        for (int mi = 0; mi < 2; mi++) {
#pragma unroll
            for (int nj = 0; nj < 4; nj++) {
                int c = cbase + nj * 8;
                long long p0 = prow[mi * 2];
                long long p1 = prow[mi * 2 + 1];
                if (p0 >= 0)
                    __stcs((float2*)(g_e + (size_t)p0 * HID + c),
                           make_float2(acc[mi][nj][0], acc[mi][nj][1]));
                if (p1 >= 0)
                    __stcs((float2*)(g_e + (size_t)p1 * HID + c),
                           make_float2(acc[mi][nj][2], acc[mi][nj][3]));
            }
        }
    }
}

// ---------------- attention gather: warp per node, sequential e, zero atomics ----------------
__global__ __launch_bounds__(256) void attn_gather_kernel(int N)
{
    int warp = threadIdx.x >> 5;
    int lane = threadIdx.x & 31;
    int n = blockIdx.x * 8 + warp;
    if (n >= N) return;
    int c = lane * 4;

    float4 q4 = *(const float4*)(g_q + (size_t)n * HID + c);
    float4 acc = make_float4(0.f, 0.f, 0.f, 0.f);
    float zacc = 0.f;

    int beg = g_off[n], end = g_off[n + 1];
    int s_next = (beg < end) ? g_srcl[beg] : 0;

#pragma unroll 2
    for (int i = beg; i < end; i++) {
        int s = s_next;
        if (i + 1 < end) s_next = g_srcl[i + 1];
        float4 e4 = __ldcs((const float4*)(g_e + (size_t)i * HID + c));
        float4 k4 = *(const float4*)(g_k + (size_t)s * HID + c);
        float4 v4 = *(const float4*)(g_v + (size_t)s * HID + c);

        float part = q4.x * (k4.x + e4.x) + q4.y * (k4.y + e4.y)
                   + q4.z * (k4.z + e4.z) + q4.w * (k4.w + e4.w);
        part += __shfl_xor_sync(0xffffffffu, part, 1);
        part += __shfl_xor_sync(0xffffffffu, part, 2);
        float a = __expf(part * 0.25f);   // /sqrt(16); alpha bounded, no max-shift needed
        zacc += a;
        acc.x += a * (v4.x + e4.x);
        acc.y += a * (v4.y + e4.y);
        acc.z += a * (v4.z + e4.z);
        acc.w += a * (v4.w + e4.w);
    }

    *(float4*)(g_num + (size_t)n * HID + c) = acc;
    if ((lane & 3) == 0) g_z[(size_t)n * NHEAD + (lane >> 2)] = zacc;
}

// ---------------- finalize ----------------
__global__ __launch_bounds__(256) void finalize_kernel(
    const float* __restrict__ x, const float* __restrict__ Wbeta,
    const float* __restrict__ gamma, const float* __restrict__ lbeta,
    float* __restrict__ out, int N)
{
    int warp = threadIdx.x >> 5;
    int lane = threadIdx.x & 31;
    int n = blockIdx.x * 8 + warp;
    if (n >= N) return;
    int c = lane * 4;

    float4 num = *(const float4*)(g_num + (size_t)n * HID + c);
    float z = g_z[(size_t)n * NHEAD + (lane >> 2)];
    float inv = z > 0.f ? 1.f / z : 0.f;
    float4 o = make_float4(num.x * inv, num.y * inv, num.z * inv, num.w * inv);
    float4 xr = *(const float4*)(g_xr + (size_t)n * HID + c);

    float4 wb0 = *(const float4*)(Wbeta + c);
    float4 wb1 = *(const float4*)(Wbeta + 128 + c);
    float4 wb2 = *(const float4*)(Wbeta + 256 + c);
    float dot = o.x * wb0.x + o.y * wb0.y + o.z * wb0.z + o.w * wb0.w
              + xr.x * wb1.x + xr.y * wb1.y + xr.z * wb1.z + xr.w * wb1.w
              + (o.x - xr.x) * wb2.x + (o.y - xr.y) * wb2.y
              + (o.z - xr.z) * wb2.z + (o.w - xr.w) * wb2.w;
#pragma unroll
    for (int m = 16; m; m >>= 1) dot += __shfl_xor_sync(0xffffffffu, dot, m);
    float beta = 1.f / (1.f + __expf(-dot));

    float4 g;
    g.x = beta * xr.x + (1.f - beta) * o.x;
    g.y = beta * xr.y + (1.f - beta) * o.y;
    g.z = beta * xr.z + (1.f - beta) * o.z;
    g.w = beta * xr.w + (1.f - beta) * o.w;

    float sgm = g.x + g.y + g.z + g.w;
#pragma unroll
    for (int m = 16; m; m >>= 1) sgm += __shfl_xor_sync(0xffffffffu, sgm, m);
    float mu = sgm * (1.f / 128.f);

    float dx = g.x - mu, dy = g.y - mu, dz = g.z - mu, dw = g.w - mu;
    float vs = dx * dx + dy * dy + dz * dz + dw * dw;
#pragma unroll
    for (int m = 16; m; m >>= 1) vs += __shfl_xor_sync(0xffffffffu, vs, m);
    float rstd = rsqrtf(vs * (1.f / 128.f) + 1e-5f);

    float4 gm = *(const float4*)(gamma + c);
    float4 lb = *(const float4*)(lbeta + c);
    float4 xin = *(const float4*)(x + (size_t)n * HID + c);

    float4 res;
    float y;
    y = dx * rstd * gm.x + lb.x; res.x = xin.x + fmaxf(y, 0.f);
    y = dy * rstd * gm.y + lb.y; res.y = xin.y + fmaxf(y, 0.f);
    y = dz * rstd * gm.z + lb.z; res.z = xin.z + fmaxf(y, 0.f);
    y = dw * rstd * gm.w + lb.w; res.w = xin.w + fmaxf(y, 0.f);
    *(float4*)(out + (size_t)n * HID + c) = res;
}

// ---------------- launch ----------------
extern "C" void kernel_launch(void* const* d_in, const int* in_sizes, int n_in,
                              void* d_out, int out_size)
{
    const float* edge_state = (const float*)d_in[0];
    const void*  idx        = d_in[1];
    const float* angle      = (const float*)d_in[2];
    const float* Wq = (const float*)d_in[3];
    const float* bq = (const float*)d_in[4];
    const float* Wk = (const float*)d_in[5];
    const float* bk = (const float*)d_in[6];
    const float* Wv = (const float*)d_in[7];
    const float* bv = (const float*)d_in[8];
    const float* We = (const float*)d_in[9];
    const float* Ws = (const float*)d_in[10];
    const float* bs = (const float*)d_in[11];
    const float* Wbeta = (const float*)d_in[12];
    const float* gamma = (const float*)d_in[13];
    const float* lbeta = (const float*)d_in[14];

    int N = in_sizes[0] / HID;
    int E = in_sizes[2] / HID;

    cudaFuncSetAttribute(node_hmma_kernel, cudaFuncAttributeMaxDynamicSharedMemorySize, SM_TOTAL);
    cudaFuncSetAttribute(egemm_hmma_kernel, cudaFuncAttributeMaxDynamicSharedMemorySize, SM_TOTAL);

    detect_kernel<<<1, 32>>>(idx, (long long)in_sizes[1]);
    prep_w_kernel<<<5, 128>>>(Wq, Wk, Wv, Ws, We);

    // CSR build (by destination), also produces edge->slot permutation
    zero_deg_kernel<<<(N + 255) / 256, 256>>>(N);
    count_kernel<<<(E + 255) / 256, 256>>>(idx, E);
    scan_kernel<<<1, 1024>>>(N, E);
    scatter_kernel<<<(E + 255) / 256, 256>>>(idx, E);

    node_hmma_kernel<<<(N + 127) / 128, 256, SM_TOTAL>>>(edge_state, bq, bk, bv, bs, N);

    egemm_hmma_kernel<<<(E + 127) / 128, 256, SM_TOTAL>>>(angle, E);

    attn_gather_kernel<<<(N + 7) / 8, 256>>>(N);

    finalize_kernel<<<(N + 7) / 8, 256>>>(edge_state, Wbeta, gamma, lbeta,
                                          (float*)d_out, N);
}

// round 10
// speedup vs baseline: 1.1360x; 1.0784x over previous
#include <cuda_runtime.h>
#include <cuda_fp16.h>
#include <cstdint>

#define HID 128
#define NHEAD 8
#define HD 16
#define MAXN 50000
#define MAXE 500000

typedef unsigned long long ull;

// ---------------- static device scratch ----------------
__device__ float g_q[MAXN * HID];
__device__ float g_k[MAXN * HID];
__device__ float g_v[MAXN * HID];
__device__ float g_xr[MAXN * HID];
__device__ float g_num[MAXN * HID];
__device__ float g_z[MAXN * NHEAD];
__device__ float g_e[(size_t)MAXE * HID];     // e rows, PERMUTED into CSR order
__device__ int   g_is64;
// CSR by destination
__device__ int g_deg[MAXN];
__device__ int g_off[MAXN + 1];
__device__ int g_pos[MAXN];
__device__ int g_srcl[MAXE];                  // src node per CSR slot
__device__ int g_perm[MAXE];                  // edge id -> CSR slot
// 5 weights: hi/lo fp16 blobs, transposed B[n][k], 128x128 swizzled (32KB each)
__device__ __half g_wt[5][2][128 * 128];

// ---------------- helpers ----------------
__device__ __forceinline__ uint32_t smem_u32(const void* p) {
    uint32_t a;
    asm("{ .reg .u64 t; cvta.to.shared.u64 t, %1; cvt.u32.u64 %0, t; }" : "=r"(a) : "l"(p));
    return a;
}

// [128 rows x 128 k] fp16 tile: two 64-k blocks of 16KB, 128B rows, XOR swizzle
__device__ __forceinline__ uint32_t swz(int row, int k) {
    uint32_t off = ((uint32_t)(k >> 6) << 14) + ((uint32_t)row << 7) + ((uint32_t)(k & 63) << 1);
    return off ^ ((off >> 3) & 0x70);
}

__device__ __forceinline__ void ldsm4(uint32_t* r, uint32_t addr) {
    asm volatile("ldmatrix.sync.aligned.m8n8.x4.shared.b16 {%0,%1,%2,%3}, [%4];"
                 : "=r"(r[0]), "=r"(r[1]), "=r"(r[2]), "=r"(r[3]) : "r"(addr));
}

__device__ __forceinline__ void mma_f16(float* d, const uint32_t* a, uint32_t b0, uint32_t b1) {
    asm("mma.sync.aligned.m16n8k16.row.col.f32.f16.f16.f32 "
        "{%0,%1,%2,%3}, {%4,%5,%6,%7}, {%8,%9}, {%0,%1,%2,%3};"
        : "+f"(d[0]), "+f"(d[1]), "+f"(d[2]), "+f"(d[3])
        : "r"(a[0]), "r"(a[1]), "r"(a[2]), "r"(a[3]), "r"(b0), "r"(b1));
}

// smem layout (GEMM kernels): A-hi 32KB | B-hi 32KB | B-lo 32KB
#define SM_AH 0
#define SM_BH 32768
#define SM_BL 65536
#define SM_TOTAL 98304

// ---------------- small kernels ----------------
__global__ void detect_kernel(const void* idx, long long total_elems) {
    if (threadIdx.x == 0 && blockIdx.x == 0) {
        const long long* p = (const long long*)idx;
        long long n = total_elems / 2;
        if (n > 256) n = 256;
        int is64 = 1;
        for (long long i = 0; i < n; i++) {
            long long v = p[i];
            if (v < 0 || v >= (1LL << 31)) is64 = 0;
        }
        g_is64 = is64;
    }
}

__global__ void zero_deg_kernel(int N) {
    int i = blockIdx.x * blockDim.x + threadIdx.x;
    if (i < N) g_deg[i] = 0;
}

__global__ void count_kernel(const void* __restrict__ idx, int E) {
    int e = blockIdx.x * 256 + threadIdx.x;
    if (e >= E) return;
    int d;
    if (g_is64) d = (int)((const long long*)idx)[e + E];
    else        d = ((const int*)idx)[e + E];
    atomicAdd(&g_deg[d], 1);
}

// single-block exclusive scan over g_deg -> g_off, g_pos
__global__ void scan_kernel(int N, int E) {
    __shared__ int sums[1024];
    int t = threadIdx.x;
    int C = (N + 1023) / 1024;
    int b = t * C;
    int hi = b + C; if (hi > N) hi = N;
    int s = 0;
    for (int i = b; i < hi; i++) s += g_deg[i];
    sums[t] = s;
    __syncthreads();
    for (int ofs = 1; ofs < 1024; ofs <<= 1) {
        int v = (t >= ofs) ? sums[t - ofs] : 0;
        __syncthreads();
        sums[t] += v;
        __syncthreads();
    }
    int run = (t == 0) ? 0 : sums[t - 1];
    for (int i = b; i < hi; i++) {
        g_off[i] = run;
        g_pos[i] = run;
        run += g_deg[i];
    }
    if (t == 1023) g_off[N] = E;
}

__global__ void scatter_kernel(const void* __restrict__ idx, int E) {
    int e = blockIdx.x * 256 + threadIdx.x;
    if (e >= E) return;
    int s, d;
    if (g_is64) {
        const long long* p = (const long long*)idx;
        s = (int)p[e]; d = (int)p[e + E];
    } else {
        const int* p = (const int*)idx;
        s = p[e]; d = p[e + E];
    }
    int p = atomicAdd(&g_pos[d], 1);
    g_srcl[p] = s;
    g_perm[e] = p;
}

// W ([in=128,out=128] row-major) -> B[n][k]=W[k][n]; fp16 hi/lo; swizzled 128x128 blobs
__global__ void prep_w_kernel(const float* W0, const float* W1, const float* W2,
                              const float* W3, const float* W4) {
    const float* W = W0;
    if (blockIdx.x == 1) W = W1;
    else if (blockIdx.x == 2) W = W2;
    else if (blockIdx.x == 3) W = W3;
    else if (blockIdx.x == 4) W = W4;
    char* hi = (char*)g_wt[blockIdx.x][0];
    char* lo = (char*)g_wt[blockIdx.x][1];
    for (int i = threadIdx.x; i < 128 * 128; i += blockDim.x) {
        int n = i & 127, k = i >> 7;
        float x = W[k * 128 + n];               // coalesced over n
        __half hv = __float2half(x);
        __half lv = __float2half(x - __half2float(hv));
        uint32_t sw = swz(n, k);
        *(__half*)(hi + sw) = hv;
        *(__half*)(lo + sw) = lv;
    }
}

// ---------------- staging ----------------
// convert A tile [128 x 128] f32 -> fp16 (hi only) into swizzled smem
__device__ __forceinline__ void stage_A(const float* __restrict__ Asrc, int rows_valid,
                                        char* sm, int tid)
{
    char* Ah = sm + SM_AH;
    for (int i = tid; i < 4096; i += 256) {
        int r = i >> 5;
        int c4 = (i & 31) << 2;
        float4 x;
        if (r < rows_valid) x = *(const float4*)(Asrc + (size_t)r * HID + c4);
        else x = make_float4(0.f, 0.f, 0.f, 0.f);
        __half2 h01 = __floats2half2_rn(x.x, x.y);
        __half2 h23 = __floats2half2_rn(x.z, x.w);
        uint32_t sw = swz(r, c4);   // 8B-aligned, 4 cols contiguous
        *(__half2*)(Ah + sw)     = h01;
        *(__half2*)(Ah + sw + 4) = h23;
    }
}

__device__ __forceinline__ void stage_B(int wi, char* sm, int tid)
{
    const float4* sH = (const float4*)g_wt[wi][0];
    const float4* sL = (const float4*)g_wt[wi][1];
    float4* dH = (float4*)(sm + SM_BH);
    float4* dL = (float4*)(sm + SM_BL);
    for (int i = tid; i < 2048; i += 256) { dH[i] = sH[i]; dL[i] = sL[i]; }
}

// ---------------- HMMA mainloop: warp tile 64x32, fp16 2-pass (hi*hi + hi*lo) ----------------
__device__ __forceinline__ void hmma_loop(uint32_t smb, int lane, int wm, int wn,
                                          float acc[4][4][4])
{
#pragma unroll
    for (int mi = 0; mi < 4; mi++)
#pragma unroll
        for (int nj = 0; nj < 4; nj++)
#pragma unroll
            for (int t = 0; t < 4; t++) acc[mi][nj][t] = 0.f;

    int arow = wm + (lane & 15);
    int acoff = (lane >> 4) << 3;
    int brow = wn + ((lane >> 4) << 3) + (lane & 7);
    int bcoff = lane & 8;

#pragma unroll
    for (int ks = 0; ks < 8; ks++) {
        int k0 = ks * 16;
        uint32_t ahi[4][4];
#pragma unroll
        for (int mi = 0; mi < 4; mi++)
            ldsm4(ahi[mi], smb + SM_AH + swz(arow + mi * 16, k0 + acoff));

        uint32_t bhi[2][4], blo[2][4];
#pragma unroll
        for (int p = 0; p < 2; p++) {
            uint32_t boff = swz(brow + p * 16, k0 + bcoff);
            ldsm4(bhi[p], smb + SM_BH + boff);
            ldsm4(blo[p], smb + SM_BL + boff);
        }

#pragma unroll
        for (int mi = 0; mi < 4; mi++) {
#pragma unroll
            for (int nj = 0; nj < 4; nj++) {
                int p = nj >> 1, hh = (nj & 1) * 2;
                mma_f16(acc[mi][nj], ahi[mi], bhi[p][hh], bhi[p][hh + 1]);
                mma_f16(acc[mi][nj], ahi[mi], blo[p][hh], blo[p][hh + 1]);
            }
        }
    }
}

// ---------------- node kernel: 4 fused projections, B resident full-width ----------------
__global__ __launch_bounds__(256, 2) void node_hmma_kernel(
    const float* __restrict__ X,
    const float* __restrict__ bq, const float* __restrict__ bk,
    const float* __restrict__ bv, const float* __restrict__ bs, int M)
{
    extern __shared__ char sm[];
    uint32_t smb = smem_u32(sm);
    int tid = threadIdx.x;
    int lane = tid & 31, w = tid >> 5;
    int wm = (w >> 2) * 64, wn = (w & 3) * 32;
    int mBase = blockIdx.x * 128;
    int rv = M - mBase; if (rv > 128) rv = 128;

    stage_A(X + (size_t)mBase * HID, rv, sm, tid);

    const float* biases[4] = {bq, bk, bv, bs};
    float* outs[4] = {g_q, g_k, g_v, g_xr};

#pragma unroll 1
    for (int wi = 0; wi < 4; wi++) {
        __syncthreads();                 // prev mma reads of B done (and A staged)
        stage_B(wi, sm, tid);
        __syncthreads();

        float acc[4][4][4];
        hmma_loop(smb, lane, wm, wn, acc);

        const float* bias = biases[wi];
        float* out = outs[wi];
        int r0 = mBase + wm + (lane >> 2);
        int cbase = wn + (lane & 3) * 2;
#pragma unroll
        for (int mi = 0; mi < 4; mi++) {
#pragma unroll
            for (int nj = 0; nj < 4; nj++) {
                int c = cbase + nj * 8;
                float b0 = __ldg(bias + c), b1 = __ldg(bias + c + 1);
                int r = r0 + mi * 16;
                if (r < M)
                    *(float2*)(out + (size_t)r * HID + c) =
                        make_float2(acc[mi][nj][0] + b0, acc[mi][nj][1] + b1);
                if (r + 8 < M)
                    *(float2*)(out + (size_t)(r + 8) * HID + c) =
                        make_float2(acc[mi][nj][2] + b0, acc[mi][nj][3] + b1);
            }
        }
    }
}

// ---------------- e-GEMM: e = angle @ We, stored PERMUTED to CSR slots ----------------
__global__ __launch_bounds__(256, 2) void egemm_hmma_kernel(
    const float* __restrict__ angle, int E)
{
    extern __shared__ char sm[];
    uint32_t smb = smem_u32(sm);
    int tid = threadIdx.x;
    int lane = tid & 31, w = tid >> 5;
    int wm = (w >> 2) * 64, wn = (w & 3) * 32;
    int eBase = blockIdx.x * 128;
    int rv = E - eBase; if (rv > 128) rv = 128;

    stage_A(angle + (size_t)eBase * HID, rv, sm, tid);
    stage_B(4, sm, tid);
    __syncthreads();

    float acc[4][4][4];
    hmma_loop(smb, lane, wm, wn, acc);

    // permuted destination rows for this thread's 8 output rows
    int r0 = eBase + wm + (lane >> 2);
    int cbase = wn + (lane & 3) * 2;
#pragma unroll
    for (int mi = 0; mi < 4; mi++) {
        int ra = r0 + mi * 16;
        int rb = ra + 8;
        long long pa = (ra < E) ? (long long)g_perm[ra] : -1;
        long long pb = (rb < E) ? (long long)g_perm[rb] : -1;
#pragma unroll
        for (int nj = 0; nj < 4; nj++) {
            int c = cbase + nj * 8;
            if (pa >= 0)
                __stcs((float2*)(g_e + (size_t)pa * HID + c),
                       make_float2(acc[mi][nj][0], acc[mi][nj][1]));
            if (pb >= 0)
                __stcs((float2*)(g_e + (size_t)pb * HID + c),
                       make_float2(acc[mi][nj][2], acc[mi][nj][3]));
        }
    }
}

// ---------------- attention gather: warp per node, sequential e, zero atomics ----------------
__global__ __launch_bounds__(256) void attn_gather_kernel(int N)
{
    int warp = threadIdx.x >> 5;
    int lane = threadIdx.x & 31;
    int n = blockIdx.x * 8 + warp;
    if (n >= N) return;
    int c = lane * 4;

    float4 q4 = *(const float4*)(g_q + (size_t)n * HID + c);
    float4 acc = make_float4(0.f, 0.f, 0.f, 0.f);
    float zacc = 0.f;

    int beg = g_off[n], end = g_off[n + 1];
    int s_next = (beg < end) ? g_srcl[beg] : 0;

#pragma unroll 2
    for (int i = beg; i < end; i++) {
        int s = s_next;
        if (i + 1 < end) s_next = g_srcl[i + 1];
        float4 e4 = __ldcs((const float4*)(g_e + (size_t)i * HID + c));
        float4 k4 = *(const float4*)(g_k + (size_t)s * HID + c);
        float4 v4 = *(const float4*)(g_v + (size_t)s * HID + c);

        float part = q4.x * (k4.x + e4.x) + q4.y * (k4.y + e4.y)
                   + q4.z * (k4.z + e4.z) + q4.w * (k4.w + e4.w);
        part += __shfl_xor_sync(0xffffffffu, part, 1);
        part += __shfl_xor_sync(0xffffffffu, part, 2);
        float a = __expf(part * 0.25f);   // /sqrt(16); alpha bounded, no max-shift needed
        zacc += a;
        acc.x += a * (v4.x + e4.x);
        acc.y += a * (v4.y + e4.y);
        acc.z += a * (v4.z + e4.z);
        acc.w += a * (v4.w + e4.w);
    }

    *(float4*)(g_num + (size_t)n * HID + c) = acc;
    if ((lane & 3) == 0) g_z[(size_t)n * NHEAD + (lane >> 2)] = zacc;
}

// ---------------- finalize ----------------
__global__ __launch_bounds__(256) void finalize_kernel(
    const float* __restrict__ x, const float* __restrict__ Wbeta,
    const float* __restrict__ gamma, const float* __restrict__ lbeta,
    float* __restrict__ out, int N)
{
    int warp = threadIdx.x >> 5;
    int lane = threadIdx.x & 31;
    int n = blockIdx.x * 8 + warp;
    if (n >= N) return;
    int c = lane * 4;

    float4 num = *(const float4*)(g_num + (size_t)n * HID + c);
    float z = g_z[(size_t)n * NHEAD + (lane >> 2)];
    float inv = z > 0.f ? 1.f / z : 0.f;
    float4 o = make_float4(num.x * inv, num.y * inv, num.z * inv, num.w * inv);
    float4 xr = *(const float4*)(g_xr + (size_t)n * HID + c);

    float4 wb0 = *(const float4*)(Wbeta + c);
    float4 wb1 = *(const float4*)(Wbeta + 128 + c);
    float4 wb2 = *(const float4*)(Wbeta + 256 + c);
    float dot = o.x * wb0.x + o.y * wb0.y + o.z * wb0.z + o.w * wb0.w
              + xr.x * wb1.x + xr.y * wb1.y + xr.z * wb1.z + xr.w * wb1.w
              + (o.x - xr.x) * wb2.x + (o.y - xr.y) * wb2.y
              + (o.z - xr.z) * wb2.z + (o.w - xr.w) * wb2.w;
#pragma unroll
    for (int m = 16; m; m >>= 1) dot += __shfl_xor_sync(0xffffffffu, dot, m);
    float beta = 1.f / (1.f + __expf(-dot));

    float4 g;
    g.x = beta * xr.x + (1.f - beta) * o.x;
    g.y = beta * xr.y + (1.f - beta) * o.y;
    g.z = beta * xr.z + (1.f - beta) * o.z;
    g.w = beta * xr.w + (1.f - beta) * o.w;

    float sgm = g.x + g.y + g.z + g.w;
#pragma unroll
    for (int m = 16; m; m >>= 1) sgm += __shfl_xor_sync(0xffffffffu, sgm, m);
    float mu = sgm * (1.f / 128.f);

    float dx = g.x - mu, dy = g.y - mu, dz = g.z - mu, dw = g.w - mu;
    float vs = dx * dx + dy * dy + dz * dz + dw * dw;
#pragma unroll
    for (int m = 16; m; m >>= 1) vs += __shfl_xor_sync(0xffffffffu, vs, m);
    float rstd = rsqrtf(vs * (1.f / 128.f) + 1e-5f);

    float4 gm = *(const float4*)(gamma + c);
    float4 lb = *(const float4*)(lbeta + c);
    float4 xin = *(const float4*)(x + (size_t)n * HID + c);

    float4 res;
    float y;
    y = dx * rstd * gm.x + lb.x; res.x = xin.x + fmaxf(y, 0.f);
    y = dy * rstd * gm.y + lb.y; res.y = xin.y + fmaxf(y, 0.f);
    y = dz * rstd * gm.z + lb.z; res.z = xin.z + fmaxf(y, 0.f);
    y = dw * rstd * gm.w + lb.w; res.w = xin.w + fmaxf(y, 0.f);
    *(float4*)(out + (size_t)n * HID + c) = res;
}

// ---------------- launch ----------------
extern "C" void kernel_launch(void* const* d_in, const int* in_sizes, int n_in,
                              void* d_out, int out_size)
{
    const float* edge_state = (const float*)d_in[0];
    const void*  idx        = d_in[1];
    const float* angle      = (const float*)d_in[2];
    const float* Wq = (const float*)d_in[3];
    const float* bq = (const float*)d_in[4];
    const float* Wk = (const float*)d_in[5];
    const float* bk = (const float*)d_in[6];
    const float* Wv = (const float*)d_in[7];
    const float* bv = (const float*)d_in[8];
    const float* We = (const float*)d_in[9];
    const float* Ws = (const float*)d_in[10];
    const float* bs = (const float*)d_in[11];
    const float* Wbeta = (const float*)d_in[12];
    const float* gamma = (const float*)d_in[13];
    const float* lbeta = (const float*)d_in[14];

    int N = in_sizes[0] / HID;
    int E = in_sizes[2] / HID;

    cudaFuncSetAttribute(node_hmma_kernel, cudaFuncAttributeMaxDynamicSharedMemorySize, SM_TOTAL);
    cudaFuncSetAttribute(egemm_hmma_kernel, cudaFuncAttributeMaxDynamicSharedMemorySize, SM_TOTAL);

    detect_kernel<<<1, 32>>>(idx, (long long)in_sizes[1]);
    prep_w_kernel<<<5, 128>>>(Wq, Wk, Wv, Ws, We);

    // CSR build (by destination), also produces edge->slot permutation
    zero_deg_kernel<<<(N + 255) / 256, 256>>>(N);
    count_kernel<<<(E + 255) / 256, 256>>>(idx, E);
    scan_kernel<<<1, 1024>>>(N, E);
    scatter_kernel<<<(E + 255) / 256, 256>>>(idx, E);

    node_hmma_kernel<<<(N + 127) / 128, 256, SM_TOTAL>>>(edge_state, bq, bk, bv, bs, N);

    egemm_hmma_kernel<<<(E + 127) / 128, 256, SM_TOTAL>>>(angle, E);

    attn_gather_kernel<<<(N + 7) / 8, 256>>>(N);

    finalize_kernel<<<(N + 7) / 8, 256>>>(edge_state, Wbeta, gamma, lbeta,
                                          (float*)d_out, N);
}

// round 11
// speedup vs baseline: 1.2137x; 1.0684x over previous
#include <cuda_runtime.h>
#include <cuda_fp16.h>
#include <cstdint>

#define HID 128
#define NHEAD 8
#define HD 16
#define MAXN 50000
#define MAXE 500000

typedef unsigned long long ull;

// ---------------- static device scratch ----------------
__device__ float g_q[MAXN * HID];
__device__ float g_k[MAXN * HID];
__device__ float g_v[MAXN * HID];
__device__ float g_xr[MAXN * HID];
__device__ float g_num[MAXN * HID];
__device__ float g_z[MAXN * NHEAD];
__device__ __half g_eh[(size_t)MAXE * HID];   // e rows fp16, PERMUTED into CSR order
__device__ int   g_is64;
// CSR by destination
__device__ int g_deg[MAXN];
__device__ int g_off[MAXN + 1];
__device__ int g_pos[MAXN];
__device__ int g_srcl[MAXE];                  // src node per CSR slot
__device__ int g_perm[MAXE];                  // edge id -> CSR slot
// 5 weights: hi/lo fp16 blobs, transposed B[n][k], 128x128 swizzled (32KB each)
__device__ __half g_wt[5][2][128 * 128];

// ---------------- helpers ----------------
__device__ __forceinline__ uint32_t smem_u32(const void* p) {
    uint32_t a;
    asm("{ .reg .u64 t; cvta.to.shared.u64 t, %1; cvt.u32.u64 %0, t; }" : "=r"(a) : "l"(p));
    return a;
}

// [128 rows x 128 k] fp16 tile: two 64-k blocks of 16KB, 128B rows, XOR swizzle
__device__ __forceinline__ uint32_t swz(int row, int k) {
    uint32_t off = ((uint32_t)(k >> 6) << 14) + ((uint32_t)row << 7) + ((uint32_t)(k & 63) << 1);
    return off ^ ((off >> 3) & 0x70);
}

__device__ __forceinline__ void ldsm4(uint32_t* r, uint32_t addr) {
    asm volatile("ldmatrix.sync.aligned.m8n8.x4.shared.b16 {%0,%1,%2,%3}, [%4];"
                 : "=r"(r[0]), "=r"(r[1]), "=r"(r[2]), "=r"(r[3]) : "r"(addr));
}

__device__ __forceinline__ void mma_f16(float* d, const uint32_t* a, uint32_t b0, uint32_t b1) {
    asm("mma.sync.aligned.m16n8k16.row.col.f32.f16.f16.f32 "
        "{%0,%1,%2,%3}, {%4,%5,%6,%7}, {%8,%9}, {%0,%1,%2,%3};"
        : "+f"(d[0]), "+f"(d[1]), "+f"(d[2]), "+f"(d[3])
        : "r"(a[0]), "r"(a[1]), "r"(a[2]), "r"(a[3]), "r"(b0), "r"(b1));
}

// smem layout (GEMM kernels): A-hi 32KB | B-hi 32KB | B-lo 32KB
#define SM_AH 0
#define SM_BH 32768
#define SM_BL 65536
#define SM_TOTAL 98304

// ---------------- small kernels ----------------
__global__ void detect_kernel(const void* idx, long long total_elems) {
    if (threadIdx.x == 0 && blockIdx.x == 0) {
        const long long* p = (const long long*)idx;
        long long n = total_elems / 2;
        if (n > 256) n = 256;
        int is64 = 1;
        for (long long i = 0; i < n; i++) {
            long long v = p[i];
            if (v < 0 || v >= (1LL << 31)) is64 = 0;
        }
        g_is64 = is64;
    }
}

__global__ void zero_deg_kernel(int N) {
    int i = blockIdx.x * blockDim.x + threadIdx.x;
    if (i < N) g_deg[i] = 0;
}

__global__ void count_kernel(const void* __restrict__ idx, int E) {
    int e = blockIdx.x * 256 + threadIdx.x;
    if (e >= E) return;
    int d;
    if (g_is64) d = (int)((const long long*)idx)[e + E];
    else        d = ((const int*)idx)[e + E];
    atomicAdd(&g_deg[d], 1);
}

// single-block exclusive scan over g_deg -> g_off, g_pos
__global__ void scan_kernel(int N, int E) {
    __shared__ int sums[1024];
    int t = threadIdx.x;
    int C = (N + 1023) / 1024;
    int b = t * C;
    int hi = b + C; if (hi > N) hi = N;
    int s = 0;
    for (int i = b; i < hi; i++) s += g_deg[i];
    sums[t] = s;
    __syncthreads();
    for (int ofs = 1; ofs < 1024; ofs <<= 1) {
        int v = (t >= ofs) ? sums[t - ofs] : 0;
        __syncthreads();
        sums[t] += v;
        __syncthreads();
    }
    int run = (t == 0) ? 0 : sums[t - 1];
    for (int i = b; i < hi; i++) {
        g_off[i] = run;
        g_pos[i] = run;
        run += g_deg[i];
    }
    if (t == 1023) g_off[N] = E;
}

__global__ void scatter_kernel(const void* __restrict__ idx, int E) {
    int e = blockIdx.x * 256 + threadIdx.x;
    if (e >= E) return;
    int s, d;
    if (g_is64) {
        const long long* p = (const long long*)idx;
        s = (int)p[e]; d = (int)p[e + E];
    } else {
        const int* p = (const int*)idx;
        s = p[e]; d = p[e + E];
    }
    int p = atomicAdd(&g_pos[d], 1);
    g_srcl[p] = s;
    g_perm[e] = p;
}

// W ([in=128,out=128] row-major) -> B[n][k]=W[k][n]; fp16 hi/lo; swizzled 128x128 blobs
__global__ void prep_w_kernel(const float* W0, const float* W1, const float* W2,
                              const float* W3, const float* W4) {
    const float* W = W0;
    if (blockIdx.x == 1) W = W1;
    else if (blockIdx.x == 2) W = W2;
    else if (blockIdx.x == 3) W = W3;
    else if (blockIdx.x == 4) W = W4;
    char* hi = (char*)g_wt[blockIdx.x][0];
    char* lo = (char*)g_wt[blockIdx.x][1];
    for (int i = threadIdx.x; i < 128 * 128; i += blockDim.x) {
        int n = i & 127, k = i >> 7;
        float x = W[k * 128 + n];               // coalesced over n
        __half hv = __float2half(x);
        __half lv = __float2half(x - __half2float(hv));
        uint32_t sw = swz(n, k);
        *(__half*)(hi + sw) = hv;
        *(__half*)(lo + sw) = lv;
    }
}

// ---------------- staging ----------------
// convert A tile [128 x 128] f32 -> fp16 (hi only) into swizzled smem
__device__ __forceinline__ void stage_A(const float* __restrict__ Asrc, int rows_valid,
                                        char* sm, int tid)
{
    char* Ah = sm + SM_AH;
    for (int i = tid; i < 4096; i += 256) {
        int r = i >> 5;
        int c4 = (i & 31) << 2;
        float4 x;
        if (r < rows_valid) x = *(const float4*)(Asrc + (size_t)r * HID + c4);
        else x = make_float4(0.f, 0.f, 0.f, 0.f);
        __half2 h01 = __floats2half2_rn(x.x, x.y);
        __half2 h23 = __floats2half2_rn(x.z, x.w);
        uint32_t sw = swz(r, c4);   // 8B-aligned, 4 cols contiguous
        *(__half2*)(Ah + sw)     = h01;
        *(__half2*)(Ah + sw + 4) = h23;
    }
}

__device__ __forceinline__ void stage_B(int wi, char* sm, int tid)
{
    const float4* sH = (const float4*)g_wt[wi][0];
    const float4* sL = (const float4*)g_wt[wi][1];
    float4* dH = (float4*)(sm + SM_BH);
    float4* dL = (float4*)(sm + SM_BL);
    for (int i = tid; i < 2048; i += 256) { dH[i] = sH[i]; dL[i] = sL[i]; }
}

// ---------------- HMMA mainloop: warp tile 64x32, fp16 2-pass (hi*hi + hi*lo) ----------------
__device__ __forceinline__ void hmma_loop(uint32_t smb, int lane, int wm, int wn,
                                          float acc[4][4][4])
{
#pragma unroll
    for (int mi = 0; mi < 4; mi++)
#pragma unroll
        for (int nj = 0; nj < 4; nj++)
#pragma unroll
            for (int t = 0; t < 4; t++) acc[mi][nj][t] = 0.f;

    int arow = wm + (lane & 15);
    int acoff = (lane >> 4) << 3;
    int brow = wn + ((lane >> 4) << 3) + (lane & 7);
    int bcoff = lane & 8;

#pragma unroll
    for (int ks = 0; ks < 8; ks++) {
        int k0 = ks * 16;
        uint32_t ahi[4][4];
#pragma unroll
        for (int mi = 0; mi < 4; mi++)
            ldsm4(ahi[mi], smb + SM_AH + swz(arow + mi * 16, k0 + acoff));

        uint32_t bhi[2][4], blo[2][4];
#pragma unroll
        for (int p = 0; p < 2; p++) {
            uint32_t boff = swz(brow + p * 16, k0 + bcoff);
            ldsm4(bhi[p], smb + SM_BH + boff);
            ldsm4(blo[p], smb + SM_BL + boff);
        }

#pragma unroll
        for (int mi = 0; mi < 4; mi++) {
#pragma unroll
            for (int nj = 0; nj < 4; nj++) {
                int p = nj >> 1, hh = (nj & 1) * 2;
                mma_f16(acc[mi][nj], ahi[mi], bhi[p][hh], bhi[p][hh + 1]);
                mma_f16(acc[mi][nj], ahi[mi], blo[p][hh], blo[p][hh + 1]);
            }
        }
    }
}

// ---------------- node kernel: 4 fused projections, B resident full-width ----------------
__global__ __launch_bounds__(256, 2) void node_hmma_kernel(
    const float* __restrict__ X,
    const float* __restrict__ bq, const float* __restrict__ bk,
    const float* __restrict__ bv, const float* __restrict__ bs, int M)
{
    extern __shared__ char sm[];
    uint32_t smb = smem_u32(sm);
    int tid = threadIdx.x;
    int lane = tid & 31, w = tid >> 5;
    int wm = (w >> 2) * 64, wn = (w & 3) * 32;
    int mBase = blockIdx.x * 128;
    int rv = M - mBase; if (rv > 128) rv = 128;

    stage_A(X + (size_t)mBase * HID, rv, sm, tid);

    const float* biases[4] = {bq, bk, bv, bs};
    float* outs[4] = {g_q, g_k, g_v, g_xr};

#pragma unroll 1
    for (int wi = 0; wi < 4; wi++) {
        __syncthreads();                 // prev mma reads of B done (and A staged)
        stage_B(wi, sm, tid);
        __syncthreads();

        float acc[4][4][4];
        hmma_loop(smb, lane, wm, wn, acc);

        const float* bias = biases[wi];
        float* out = outs[wi];
        int r0 = mBase + wm + (lane >> 2);
        int cbase = wn + (lane & 3) * 2;
#pragma unroll
        for (int mi = 0; mi < 4; mi++) {
#pragma unroll
            for (int nj = 0; nj < 4; nj++) {
                int c = cbase + nj * 8;
                float b0 = __ldg(bias + c), b1 = __ldg(bias + c + 1);
                int r = r0 + mi * 16;
                if (r < M)
                    *(float2*)(out + (size_t)r * HID + c) =
                        make_float2(acc[mi][nj][0] + b0, acc[mi][nj][1] + b1);
                if (r + 8 < M)
                    *(float2*)(out + (size_t)(r + 8) * HID + c) =
                        make_float2(acc[mi][nj][2] + b0, acc[mi][nj][3] + b1);
            }
        }
    }
}

// ---------------- e-GEMM: e = angle @ We, fp16 stores PERMUTED to CSR slots ----------------
__global__ __launch_bounds__(256, 2) void egemm_hmma_kernel(
    const float* __restrict__ angle, int E)
{
    extern __shared__ char sm[];
    uint32_t smb = smem_u32(sm);
    int tid = threadIdx.x;
    int lane = tid & 31, w = tid >> 5;
    int wm = (w >> 2) * 64, wn = (w & 3) * 32;
    int eBase = blockIdx.x * 128;
    int rv = E - eBase; if (rv > 128) rv = 128;

    stage_A(angle + (size_t)eBase * HID, rv, sm, tid);
    stage_B(4, sm, tid);
    __syncthreads();

    float acc[4][4][4];
    hmma_loop(smb, lane, wm, wn, acc);

    // permuted destination rows for this thread's 8 output rows
    int r0 = eBase + wm + (lane >> 2);
    int cbase = wn + (lane & 3) * 2;
#pragma unroll
    for (int mi = 0; mi < 4; mi++) {
        int ra = r0 + mi * 16;
        int rb = ra + 8;
        long long pa = (ra < E) ? (long long)g_perm[ra] : -1;
        long long pb = (rb < E) ? (long long)g_perm[rb] : -1;
#pragma unroll
        for (int nj = 0; nj < 4; nj++) {
            int c = cbase + nj * 8;
            if (pa >= 0) {
                __half2 h = __floats2half2_rn(acc[mi][nj][0], acc[mi][nj][1]);
                uint32_t u = *(uint32_t*)&h;
                asm volatile("st.global.cs.u32 [%0], %1;"
                             :: "l"(g_eh + (size_t)pa * HID + c), "r"(u) : "memory");
            }
            if (pb >= 0) {
                __half2 h = __floats2half2_rn(acc[mi][nj][2], acc[mi][nj][3]);
                uint32_t u = *(uint32_t*)&h;
                asm volatile("st.global.cs.u32 [%0], %1;"
                             :: "l"(g_eh + (size_t)pb * HID + c), "r"(u) : "memory");
            }
        }
    }
}

// ---------------- attention gather: warp/node, 2-edge pipelined, fp16 e ----------------
__global__ __launch_bounds__(256) void attn_gather_kernel(int N)
{
    int warp = threadIdx.x >> 5;
    int lane = threadIdx.x & 31;
    int n = blockIdx.x * 8 + warp;
    if (n >= N) return;
    int c = lane * 4;

    float4 q4 = *(const float4*)(g_q + (size_t)n * HID + c);
    float4 acc = make_float4(0.f, 0.f, 0.f, 0.f);
    float zacc = 0.f;

    int beg = g_off[n], end = g_off[n + 1];
    int i = beg;

    // 2-edge pipelined main loop: all 6 gathers issued before compute
    for (; i + 2 <= end; i += 2) {
        int s0 = g_srcl[i];
        int s1 = g_srcl[i + 1];
        uint2 eu0 = __ldcs((const uint2*)(g_eh + (size_t)i * HID + c));
        uint2 eu1 = __ldcs((const uint2*)(g_eh + (size_t)(i + 1) * HID + c));
        float4 k0 = *(const float4*)(g_k + (size_t)s0 * HID + c);
        float4 v0 = *(const float4*)(g_v + (size_t)s0 * HID + c);
        float4 k1 = *(const float4*)(g_k + (size_t)s1 * HID + c);
        float4 v1 = *(const float4*)(g_v + (size_t)s1 * HID + c);

        float2 ea0 = __half22float2(*(__half2*)&eu0.x);
        float2 eb0 = __half22float2(*(__half2*)&eu0.y);
        float2 ea1 = __half22float2(*(__half2*)&eu1.x);
        float2 eb1 = __half22float2(*(__half2*)&eu1.y);

        float p0 = q4.x * (k0.x + ea0.x) + q4.y * (k0.y + ea0.y)
                 + q4.z * (k0.z + eb0.x) + q4.w * (k0.w + eb0.y);
        float p1 = q4.x * (k1.x + ea1.x) + q4.y * (k1.y + ea1.y)
                 + q4.z * (k1.z + eb1.x) + q4.w * (k1.w + eb1.y);
        p0 += __shfl_xor_sync(0xffffffffu, p0, 1);
        p1 += __shfl_xor_sync(0xffffffffu, p1, 1);
        p0 += __shfl_xor_sync(0xffffffffu, p0, 2);
        p1 += __shfl_xor_sync(0xffffffffu, p1, 2);
        float a0 = __expf(p0 * 0.25f);   // /sqrt(16); alpha bounded, no max-shift needed
        float a1 = __expf(p1 * 0.25f);
        zacc += a0 + a1;
        acc.x += a0 * (v0.x + ea0.x) + a1 * (v1.x + ea1.x);
        acc.y += a0 * (v0.y + ea0.y) + a1 * (v1.y + ea1.y);
        acc.z += a0 * (v0.z + eb0.x) + a1 * (v1.z + eb1.x);
        acc.w += a0 * (v0.w + eb0.y) + a1 * (v1.w + eb1.y);
    }
    // tail
    if (i < end) {
        int s = g_srcl[i];
        uint2 eu = __ldcs((const uint2*)(g_eh + (size_t)i * HID + c));
        float4 k4 = *(const float4*)(g_k + (size_t)s * HID + c);
        float4 v4 = *(const float4*)(g_v + (size_t)s * HID + c);
        float2 ea = __half22float2(*(__half2*)&eu.x);
        float2 eb = __half22float2(*(__half2*)&eu.y);
        float p = q4.x * (k4.x + ea.x) + q4.y * (k4.y + ea.y)
                + q4.z * (k4.z + eb.x) + q4.w * (k4.w + eb.y);
        p += __shfl_xor_sync(0xffffffffu, p, 1);
        p += __shfl_xor_sync(0xffffffffu, p, 2);
        float a = __expf(p * 0.25f);
        zacc += a;
        acc.x += a * (v4.x + ea.x);
        acc.y += a * (v4.y + ea.y);
        acc.z += a * (v4.z + eb.x);
        acc.w += a * (v4.w + eb.y);
    }

    *(float4*)(g_num + (size_t)n * HID + c) = acc;
    if ((lane & 3) == 0) g_z[(size_t)n * NHEAD + (lane >> 2)] = zacc;
}

// ---------------- finalize ----------------
__global__ __launch_bounds__(256) void finalize_kernel(
    const float* __restrict__ x, const float* __restrict__ Wbeta,
    const float* __restrict__ gamma, const float* __restrict__ lbeta,
    float* __restrict__ out, int N)
{
    int warp = threadIdx.x >> 5;
    int lane = threadIdx.x & 31;
    int n = blockIdx.x * 8 + warp;
    if (n >= N) return;
    int c = lane * 4;

    float4 num = *(const float4*)(g_num + (size_t)n * HID + c);
    float z = g_z[(size_t)n * NHEAD + (lane >> 2)];
    float inv = z > 0.f ? 1.f / z : 0.f;
    float4 o = make_float4(num.x * inv, num.y * inv, num.z * inv, num.w * inv);
    float4 xr = *(const float4*)(g_xr + (size_t)n * HID + c);

    float4 wb0 = *(const float4*)(Wbeta + c);
    float4 wb1 = *(const float4*)(Wbeta + 128 + c);
    float4 wb2 = *(const float4*)(Wbeta + 256 + c);
    float dot = o.x * wb0.x + o.y * wb0.y + o.z * wb0.z + o.w * wb0.w
              + xr.x * wb1.x + xr.y * wb1.y + xr.z * wb1.z + xr.w * wb1.w
              + (o.x - xr.x) * wb2.x + (o.y - xr.y) * wb2.y
              + (o.z - xr.z) * wb2.z + (o.w - xr.w) * wb2.w;
#pragma unroll
    for (int m = 16; m; m >>= 1) dot += __shfl_xor_sync(0xffffffffu, dot, m);
    float beta = 1.f / (1.f + __expf(-dot));

    float4 g;
    g.x = beta * xr.x + (1.f - beta) * o.x;
    g.y = beta * xr.y + (1.f - beta) * o.y;
    g.z = beta * xr.z + (1.f - beta) * o.z;
    g.w = beta * xr.w + (1.f - beta) * o.w;

    float sgm = g.x + g.y + g.z + g.w;
#pragma unroll
    for (int m = 16; m; m >>= 1) sgm += __shfl_xor_sync(0xffffffffu, sgm, m);
    float mu = sgm * (1.f / 128.f);

    float dx = g.x - mu, dy = g.y - mu, dz = g.z - mu, dw = g.w - mu;
    float vs = dx * dx + dy * dy + dz * dz + dw * dw;
#pragma unroll
    for (int m = 16; m; m >>= 1) vs += __shfl_xor_sync(0xffffffffu, vs, m);
    float rstd = rsqrtf(vs * (1.f / 128.f) + 1e-5f);

    float4 gm = *(const float4*)(gamma + c);
    float4 lb = *(const float4*)(lbeta + c);
    float4 xin = *(const float4*)(x + (size_t)n * HID + c);

    float4 res;
    float y;
    y = dx * rstd * gm.x + lb.x; res.x = xin.x + fmaxf(y, 0.f);
    y = dy * rstd * gm.y + lb.y; res.y = xin.y + fmaxf(y, 0.f);
    y = dz * rstd * gm.z + lb.z; res.z = xin.z + fmaxf(y, 0.f);
    y = dw * rstd * gm.w + lb.w; res.w = xin.w + fmaxf(y, 0.f);
    *(float4*)(out + (size_t)n * HID + c) = res;
}

// ---------------- launch ----------------
extern "C" void kernel_launch(void* const* d_in, const int* in_sizes, int n_in,
                              void* d_out, int out_size)
{
    const float* edge_state = (const float*)d_in[0];
    const void*  idx        = d_in[1];
    const float* angle      = (const float*)d_in[2];
    const float* Wq = (const float*)d_in[3];
    const float* bq = (const float*)d_in[4];
    const float* Wk = (const float*)d_in[5];
    const float* bk = (const float*)d_in[6];
    const float* Wv = (const float*)d_in[7];
    const float* bv = (const float*)d_in[8];
    const float* We = (const float*)d_in[9];
    const float* Ws = (const float*)d_in[10];
    const float* bs = (const float*)d_in[11];
    const float* Wbeta = (const float*)d_in[12];
    const float* gamma = (const float*)d_in[13];
    const float* lbeta = (const float*)d_in[14];

    int N = in_sizes[0] / HID;
    int E = in_sizes[2] / HID;

    cudaFuncSetAttribute(node_hmma_kernel, cudaFuncAttributeMaxDynamicSharedMemorySize, SM_TOTAL);
    cudaFuncSetAttribute(egemm_hmma_kernel, cudaFuncAttributeMaxDynamicSharedMemorySize, SM_TOTAL);

    detect_kernel<<<1, 32>>>(idx, (long long)in_sizes[1]);
    prep_w_kernel<<<5, 128>>>(Wq, Wk, Wv, Ws, We);

    // CSR build (by destination), also produces edge->slot permutation
    zero_deg_kernel<<<(N + 255) / 256, 256>>>(N);
    count_kernel<<<(E + 255) / 256, 256>>>(idx, E);
    scan_kernel<<<1, 1024>>>(N, E);
    scatter_kernel<<<(E + 255) / 256, 256>>>(idx, E);

    node_hmma_kernel<<<(N + 127) / 128, 256, SM_TOTAL>>>(edge_state, bq, bk, bv, bs, N);

    egemm_hmma_kernel<<<(E + 127) / 128, 256, SM_TOTAL>>>(angle, E);

    attn_gather_kernel<<<(N + 7) / 8, 256>>>(N);

    finalize_kernel<<<(N + 7) / 8, 256>>>(edge_state, Wbeta, gamma, lbeta,
                                          (float*)d_out, N);
}